// round 1
// baseline (speedup 1.0000x reference)
#include <cuda_runtime.h>
#include <cuda_bf16.h>
#include <math_constants.h>

// Problem constants
#define Bv 4
#define Tv 2048
#define Dv 1024
#define Hv 16
#define HDv 64
#define MTOK (Bv*Tv)          // 8192 rows

// ---------------- scratch (no allocation allowed) ----------------
__device__ float g_q[(size_t)MTOK * Dv];
__device__ float g_k[(size_t)MTOK * Dv];
__device__ float g_v[(size_t)MTOK * Dv];
__device__ float g_o[(size_t)MTOK * Dv];

// ---------------- SGEMM: C[M,N] = A[M,K] * W[N,K]^T + bias ----------------
// 128x128 block, 256 threads, 8x8 per thread, BK=16
__global__ __launch_bounds__(256) void sgemm_bias_kernel(
    const float* __restrict__ A, const float* __restrict__ W,
    const float* __restrict__ bias, float* __restrict__ C,
    int M, int N, int K)
{
    __shared__ float As[16][128];
    __shared__ float Bs[16][128];

    const int tid = threadIdx.x;
    const int tx = tid & 15;      // 0..15 -> N tile
    const int ty = tid >> 4;      // 0..15 -> M tile
    const int row0 = blockIdx.y * 128 + ty * 8;
    const int col0 = blockIdx.x * 128 + tx * 8;

    const int l_row  = tid >> 2;            // 0..63
    const int l_col4 = (tid & 3) * 4;       // 0,4,8,12

    const float* Aptr = A + (size_t)(blockIdx.y * 128) * K;
    const float* Wptr = W + (size_t)(blockIdx.x * 128) * K;

    float acc[8][8];
    #pragma unroll
    for (int i = 0; i < 8; i++)
        #pragma unroll
        for (int j = 0; j < 8; j++) acc[i][j] = 0.f;

    for (int k0 = 0; k0 < K; k0 += 16) {
        #pragma unroll
        for (int i = 0; i < 2; i++) {
            int r = l_row + i * 64;
            float4 va = *(const float4*)(Aptr + (size_t)r * K + k0 + l_col4);
            As[l_col4 + 0][r] = va.x;
            As[l_col4 + 1][r] = va.y;
            As[l_col4 + 2][r] = va.z;
            As[l_col4 + 3][r] = va.w;
            float4 vw = *(const float4*)(Wptr + (size_t)r * K + k0 + l_col4);
            Bs[l_col4 + 0][r] = vw.x;
            Bs[l_col4 + 1][r] = vw.y;
            Bs[l_col4 + 2][r] = vw.z;
            Bs[l_col4 + 3][r] = vw.w;
        }
        __syncthreads();

        #pragma unroll
        for (int k = 0; k < 16; k++) {
            float a[8], b[8];
            *(float4*)(a)     = *(const float4*)&As[k][ty * 8];
            *(float4*)(a + 4) = *(const float4*)&As[k][ty * 8 + 4];
            *(float4*)(b)     = *(const float4*)&Bs[k][tx * 8];
            *(float4*)(b + 4) = *(const float4*)&Bs[k][tx * 8 + 4];
            #pragma unroll
            for (int i = 0; i < 8; i++)
                #pragma unroll
                for (int j = 0; j < 8; j++)
                    acc[i][j] += a[i] * b[j];
        }
        __syncthreads();
    }

    float bv8[8];
    *(float4*)(bv8)     = *(const float4*)(bias + col0);
    *(float4*)(bv8 + 4) = *(const float4*)(bias + col0 + 4);

    #pragma unroll
    for (int i = 0; i < 8; i++) {
        int m = row0 + i;
        float4 o0, o1;
        o0.x = acc[i][0] + bv8[0]; o0.y = acc[i][1] + bv8[1];
        o0.z = acc[i][2] + bv8[2]; o0.w = acc[i][3] + bv8[3];
        o1.x = acc[i][4] + bv8[4]; o1.y = acc[i][5] + bv8[5];
        o1.z = acc[i][6] + bv8[6]; o1.w = acc[i][7] + bv8[7];
        *(float4*)(C + (size_t)m * N + col0)     = o0;
        *(float4*)(C + (size_t)m * N + col0 + 4) = o1;
    }
}

// ---------------- fused flash attention ----------------
// grid: (T/64 query blocks, B*H). block: 256 threads.
// Layout: Q/K/V stored [B,T,D] with head h at column offset h*HD.
#define BQ 64
#define BKV 64
#define SPAD 68
#define ATTN_SMEM (4 * BQ * SPAD * (int)sizeof(float))   // sQ, sK, sV, sP

__global__ __launch_bounds__(256) void attn_kernel(
    const float* __restrict__ Q, const float* __restrict__ K,
    const float* __restrict__ V, float* __restrict__ O)
{
    extern __shared__ float sm[];
    float* sQ = sm;
    float* sK = sQ + BQ * SPAD;
    float* sV = sK + BKV * SPAD;
    float* sP = sV + BKV * SPAD;

    const int tid = threadIdx.x;
    const int bh  = blockIdx.y;
    const int b   = bh / Hv;
    const int h   = bh % Hv;
    const int q0  = blockIdx.x * BQ;

    const int tq = tid >> 4;   // 0..15 : owns queries 4*tq..4*tq+3
    const int tj = tid & 15;   // 0..15 : owns key/dim slice 4*tj..4*tj+3

    const float* Qb = Q + ((size_t)b * Tv) * Dv + h * HDv;
    const float* Kb = K + ((size_t)b * Tv) * Dv + h * HDv;
    const float* Vb = V + ((size_t)b * Tv) * Dv + h * HDv;

    // load Q tile [64 x 64]
    #pragma unroll
    for (int i = 0; i < 4; i++) {
        int f  = tid + i * 256;
        int r  = f >> 4;
        int c4 = (f & 15) * 4;
        *(float4*)&sQ[r * SPAD + c4] =
            *(const float4*)(Qb + (size_t)(q0 + r) * Dv + c4);
    }

    float m_i[4], l_i[4], acc[4][4];
    #pragma unroll
    for (int qq = 0; qq < 4; qq++) {
        m_i[qq] = -1e30f; l_i[qq] = 0.f;
        #pragma unroll
        for (int dd = 0; dd < 4; dd++) acc[qq][dd] = 0.f;
    }

    for (int kv0 = 0; kv0 < Tv; kv0 += BKV) {
        __syncthreads();   // previous iter done reading sK/sV/sP
        #pragma unroll
        for (int i = 0; i < 4; i++) {
            int f  = tid + i * 256;
            int r  = f >> 4;
            int c4 = (f & 15) * 4;
            *(float4*)&sK[r * SPAD + c4] =
                *(const float4*)(Kb + (size_t)(kv0 + r) * Dv + c4);
            *(float4*)&sV[r * SPAD + c4] =
                *(const float4*)(Vb + (size_t)(kv0 + r) * Dv + c4);
        }
        __syncthreads();

        // ---- S = (Q K^T) * 1/8 : 4x4 tile per thread ----
        float s[4][4];
        #pragma unroll
        for (int qq = 0; qq < 4; qq++)
            #pragma unroll
            for (int jj = 0; jj < 4; jj++) s[qq][jj] = 0.f;

        #pragma unroll 4
        for (int k4 = 0; k4 < 16; k4++) {
            float qv[4][4], kv[4][4];
            #pragma unroll
            for (int qq = 0; qq < 4; qq++) {
                float4 t = *(const float4*)&sQ[(4 * tq + qq) * SPAD + k4 * 4];
                qv[qq][0] = t.x; qv[qq][1] = t.y; qv[qq][2] = t.z; qv[qq][3] = t.w;
            }
            #pragma unroll
            for (int jj = 0; jj < 4; jj++) {
                float4 t = *(const float4*)&sK[(4 * tj + jj) * SPAD + k4 * 4];
                kv[jj][0] = t.x; kv[jj][1] = t.y; kv[jj][2] = t.z; kv[jj][3] = t.w;
            }
            #pragma unroll
            for (int qq = 0; qq < 4; qq++)
                #pragma unroll
                for (int jj = 0; jj < 4; jj++)
                    #pragma unroll
                    for (int kk = 0; kk < 4; kk++)
                        s[qq][jj] += qv[qq][kk] * kv[jj][kk];
        }

        // ---- online softmax (row stats across the 16 lanes sharing tq) ----
        #pragma unroll
        for (int qq = 0; qq < 4; qq++) {
            float mx = -1e30f;
            #pragma unroll
            for (int jj = 0; jj < 4; jj++) {
                s[qq][jj] *= 0.125f;           // 1/sqrt(64)
                mx = fmaxf(mx, s[qq][jj]);
            }
            #pragma unroll
            for (int off = 8; off > 0; off >>= 1)
                mx = fmaxf(mx, __shfl_xor_sync(0xffffffffu, mx, off));

            float mnew  = fmaxf(m_i[qq], mx);
            float alpha = __expf(m_i[qq] - mnew);
            m_i[qq] = mnew;

            float lsum = 0.f;
            #pragma unroll
            for (int jj = 0; jj < 4; jj++) {
                float p = __expf(s[qq][jj] - mnew);
                s[qq][jj] = p;
                lsum += p;
            }
            l_i[qq] = l_i[qq] * alpha + lsum;
            #pragma unroll
            for (int dd = 0; dd < 4; dd++) acc[qq][dd] *= alpha;
        }

        // write P tile to smem
        #pragma unroll
        for (int qq = 0; qq < 4; qq++) {
            float4 t;
            t.x = s[qq][0]; t.y = s[qq][1]; t.z = s[qq][2]; t.w = s[qq][3];
            *(float4*)&sP[(4 * tq + qq) * SPAD + 4 * tj] = t;
        }
        __syncthreads();

        // ---- O += P @ V : thread owns 4 queries x 4 dims ----
        #pragma unroll 4
        for (int j4 = 0; j4 < 16; j4++) {
            float p[4][4], vv[4][4];
            #pragma unroll
            for (int qq = 0; qq < 4; qq++) {
                float4 t = *(const float4*)&sP[(4 * tq + qq) * SPAD + 4 * j4];
                p[qq][0] = t.x; p[qq][1] = t.y; p[qq][2] = t.z; p[qq][3] = t.w;
            }
            #pragma unroll
            for (int jj = 0; jj < 4; jj++) {
                float4 t = *(const float4*)&sV[(4 * j4 + jj) * SPAD + 4 * tj];
                vv[jj][0] = t.x; vv[jj][1] = t.y; vv[jj][2] = t.z; vv[jj][3] = t.w;
            }
            #pragma unroll
            for (int qq = 0; qq < 4; qq++)
                #pragma unroll
                for (int dd = 0; dd < 4; dd++)
                    #pragma unroll
                    for (int jj = 0; jj < 4; jj++)
                        acc[qq][dd] += p[qq][jj] * vv[jj][dd];
        }
    }

    // ---- finalize: divide by row sum, write O[B,T,D] ----
    float* Ob = O + ((size_t)b * Tv) * Dv + h * HDv;
    #pragma unroll
    for (int qq = 0; qq < 4; qq++) {
        float l = l_i[qq];
        #pragma unroll
        for (int off = 8; off > 0; off >>= 1)
            l += __shfl_xor_sync(0xffffffffu, l, off);
        float inv = 1.0f / l;
        float4 o;
        o.x = acc[qq][0] * inv; o.y = acc[qq][1] * inv;
        o.z = acc[qq][2] * inv; o.w = acc[qq][3] * inv;
        *(float4*)(Ob + (size_t)(q0 + 4 * tq + qq) * Dv + 4 * tj) = o;
    }
}

// ---------------- launch ----------------
extern "C" void kernel_launch(void* const* d_in, const int* in_sizes, int n_in,
                              void* d_out, int out_size)
{
    const float* x  = (const float*)d_in[0];
    const float* Wq = (const float*)d_in[1];
    const float* bq = (const float*)d_in[2];
    const float* Wk = (const float*)d_in[3];
    const float* bk = (const float*)d_in[4];
    const float* Wv = (const float*)d_in[5];
    const float* bv = (const float*)d_in[6];
    const float* Wo = (const float*)d_in[7];
    const float* bo = (const float*)d_in[8];
    float* out = (float*)d_out;

    float *q, *k, *v, *o;
    cudaGetSymbolAddress((void**)&q, g_q);
    cudaGetSymbolAddress((void**)&k, g_k);
    cudaGetSymbolAddress((void**)&v, g_v);
    cudaGetSymbolAddress((void**)&o, g_o);

    dim3 ggrid(Dv / 128, MTOK / 128);   // (8, 64)
    sgemm_bias_kernel<<<ggrid, 256>>>(x, Wq, bq, q, MTOK, Dv, Dv);
    sgemm_bias_kernel<<<ggrid, 256>>>(x, Wk, bk, k, MTOK, Dv, Dv);
    sgemm_bias_kernel<<<ggrid, 256>>>(x, Wv, bv, v, MTOK, Dv, Dv);

    cudaFuncSetAttribute(attn_kernel,
                         cudaFuncAttributeMaxDynamicSharedMemorySize, ATTN_SMEM);
    dim3 agrid(Tv / BQ, Bv * Hv);       // (32, 64)
    attn_kernel<<<agrid, 256, ATTN_SMEM>>>(q, k, v, o);

    sgemm_bias_kernel<<<ggrid, 256>>>(o, Wo, bo, out, MTOK, Dv, Dv);
}

// round 6
// speedup vs baseline: 1.8991x; 1.8991x over previous
#include <cuda_runtime.h>
#include <cuda_bf16.h>
#include <stdint.h>

// Problem constants
#define Bv 4
#define Tv 2048
#define Dv 1024
#define Hv 16
#define HDv 64
#define MTOK (Bv*Tv)          // 8192 rows

// ---------------- scratch (no allocation allowed) ----------------
__device__ float g_q[(size_t)MTOK * Dv];
__device__ float g_k[(size_t)MTOK * Dv];
__device__ float g_v[(size_t)MTOK * Dv];
__device__ float g_o[(size_t)MTOK * Dv];

// ================= helpers =================
__device__ __forceinline__ uint32_t smem_u32(const void* p) {
    uint32_t a;
    asm("{ .reg .u64 t; cvta.to.shared.u64 t, %1; cvt.u32.u64 %0, t; }"
        : "=r"(a) : "l"(p));
    return a;
}

#define SW128(o) ((o) ^ (((o) >> 3) & 0x70))

#define LDSM4(r, addr) \
    asm volatile("ldmatrix.sync.aligned.m8n8.x4.shared.b16 {%0,%1,%2,%3}, [%4];" \
        : "=r"((r)[0]), "=r"((r)[1]), "=r"((r)[2]), "=r"((r)[3]) : "r"(addr))

#define LDSM2(r, addr) \
    asm volatile("ldmatrix.sync.aligned.m8n8.x2.shared.b16 {%0,%1}, [%2];" \
        : "=r"((r)[0]), "=r"((r)[1]) : "r"(addr))

#define MMA_BF16(d, a, b) \
    asm volatile("mma.sync.aligned.m16n8k16.row.col.f32.bf16.bf16.f32 " \
        "{%0,%1,%2,%3}, {%4,%5,%6,%7}, {%8,%9}, {%0,%1,%2,%3};" \
        : "+f"((d)[0]), "+f"((d)[1]), "+f"((d)[2]), "+f"((d)[3]) \
        : "r"((a)[0]), "r"((a)[1]), "r"((a)[2]), "r"((a)[3]), \
          "r"((b)[0]), "r"((b)[1]))

// split fp32 -> (hi, lo) bf16 pairs, packed for 8B smem stores
__device__ __forceinline__ void split4(float4 v, uint2& h, uint2& l) {
    __nv_bfloat16 hx = __float2bfloat16_rn(v.x);
    __nv_bfloat16 hy = __float2bfloat16_rn(v.y);
    __nv_bfloat16 hz = __float2bfloat16_rn(v.z);
    __nv_bfloat16 hw = __float2bfloat16_rn(v.w);
    __nv_bfloat162 h0; h0.x = hx; h0.y = hy;
    __nv_bfloat162 h1; h1.x = hz; h1.y = hw;
    __nv_bfloat162 l0;
    l0.x = __float2bfloat16_rn(v.x - __bfloat162float(hx));
    l0.y = __float2bfloat16_rn(v.y - __bfloat162float(hy));
    __nv_bfloat162 l1;
    l1.x = __float2bfloat16_rn(v.z - __bfloat162float(hz));
    l1.y = __float2bfloat16_rn(v.w - __bfloat162float(hw));
    h.x = *reinterpret_cast<uint32_t*>(&h0);
    h.y = *reinterpret_cast<uint32_t*>(&h1);
    l.x = *reinterpret_cast<uint32_t*>(&l0);
    l.y = *reinterpret_cast<uint32_t*>(&l1);
}

// ================= HMMA GEMM: C[M,1024] = A[M,1024] @ W[1024,1024]^T + bias =================
// 128x128 CTA tile, 8 warps (2m x 4n), warp tile 64x32, BK=64, split-bf16 (3 MMAs).
#define GT 16384                 // one 128-row x 128B bf16 tile
#define GSMEM (4 * GT + 1024)    // AH, AL, WH, WL + alignment slack

__global__ __launch_bounds__(256) void gemm_mma(
    const float* __restrict__ A, const float* __restrict__ W,
    const float* __restrict__ bias, float* __restrict__ C)
{
    extern __shared__ char dsm[];
    uint32_t dynb = smem_u32(dsm);
    uint32_t base = (dynb + 1023) & ~1023u;
    char* st = dsm + (base - dynb);
    const uint32_t sb = base;

    const int tid  = threadIdx.x;
    const int wid  = tid >> 5;
    const int lane = tid & 31;
    const int wm   = wid >> 2;        // 0..1
    const int wn   = wid & 3;         // 0..3

    const int rowBase = blockIdx.y * 128;
    const int colBase = blockIdx.x * 128;
    const float* Ab = A + (size_t)rowBase * Dv;
    const float* Wb = W + (size_t)colBase * Dv;

    const int r0 = tid >> 4;          // 0..15
    const int c4 = (tid & 15) * 4;    // 0..60  (float col within 64-chunk)

    float acc[4][4][4];
    #pragma unroll
    for (int mt = 0; mt < 4; mt++)
        #pragma unroll
        for (int nt = 0; nt < 4; nt++)
            #pragma unroll
            for (int j = 0; j < 4; j++) acc[mt][nt][j] = 0.f;

    // prefetch chunk 0
    float4 av[8], wv[8];
    #pragma unroll
    for (int i = 0; i < 8; i++) {
        av[i] = *(const float4*)(Ab + (size_t)(r0 + 16 * i) * Dv + c4);
        wv[i] = *(const float4*)(Wb + (size_t)(r0 + 16 * i) * Dv + c4);
    }

    for (int c = 0; c < 16; c++) {
        __syncthreads();   // previous MMA phase done reading smem

        // convert + swizzled STS
        #pragma unroll
        for (int i = 0; i < 8; i++) {
            int row = r0 + 16 * i;
            uint32_t off = SW128((uint32_t)(row * 128 + (tid & 15) * 8));
            uint2 h, l;
            split4(av[i], h, l);
            *(uint2*)(st + off)          = h;
            *(uint2*)(st + GT + off)     = l;
            split4(wv[i], h, l);
            *(uint2*)(st + 2 * GT + off) = h;
            *(uint2*)(st + 3 * GT + off) = l;
        }
        __syncthreads();

        // prefetch next chunk (latency hidden by MMA phase)
        if (c < 15) {
            const float* Ap = Ab + (c + 1) * 64 + c4;
            const float* Wp = Wb + (c + 1) * 64 + c4;
            #pragma unroll
            for (int i = 0; i < 8; i++) {
                av[i] = *(const float4*)(Ap + (size_t)(r0 + 16 * i) * Dv);
                wv[i] = *(const float4*)(Wp + (size_t)(r0 + 16 * i) * Dv);
            }
        }

        // MMA phase: 4 k-steps of 16
        #pragma unroll
        for (int ks = 0; ks < 4; ks++) {
            uint32_t aH[4][4], aL[4][4], bH[4][2], bL[4][2];

            const int arow = wm * 64 + (lane & 15);
            const uint32_t akb = ks * 32 + ((lane >> 4) << 4);
            #pragma unroll
            for (int mt = 0; mt < 4; mt++) {
                uint32_t o = SW128((uint32_t)((arow + mt * 16) * 128) + akb);
                LDSM4(aH[mt], sb + o);
                LDSM4(aL[mt], sb + GT + o);
            }

            const int brow = wn * 32 + (lane & 7);
            const uint32_t bkb = ks * 32 + ((lane >> 3) & 1) * 16;
            #pragma unroll
            for (int nt = 0; nt < 4; nt++) {
                uint32_t o = SW128((uint32_t)((brow + nt * 8) * 128) + bkb);
                LDSM2(bH[nt], sb + 2 * GT + o);
                LDSM2(bL[nt], sb + 3 * GT + o);
            }

            #pragma unroll
            for (int mt = 0; mt < 4; mt++)
                #pragma unroll
                for (int nt = 0; nt < 4; nt++) {
                    MMA_BF16(acc[mt][nt], aH[mt], bH[nt]);
                    MMA_BF16(acc[mt][nt], aH[mt], bL[nt]);
                    MMA_BF16(acc[mt][nt], aL[mt], bH[nt]);
                }
        }
    }

    // epilogue: c-frag m16n8: d0,d1 -> (row, col..col+1); d2,d3 -> (row+8, ..)
    #pragma unroll
    for (int mt = 0; mt < 4; mt++) {
        #pragma unroll
        for (int nt = 0; nt < 4; nt++) {
            int row = rowBase + wm * 64 + mt * 16 + (lane >> 2);
            int col = colBase + wn * 32 + nt * 8 + (lane & 3) * 2;
            float2 b2 = *(const float2*)(bias + col);
            float2 o0, o1;
            o0.x = acc[mt][nt][0] + b2.x; o0.y = acc[mt][nt][1] + b2.y;
            o1.x = acc[mt][nt][2] + b2.x; o1.y = acc[mt][nt][3] + b2.y;
            *(float2*)(C + (size_t)row * Dv + col)       = o0;
            *(float2*)(C + (size_t)(row + 8) * Dv + col) = o1;
        }
    }
}

// ================= fused flash attention (conflict-free smem) =================
#define BQ 64
#define BKV 64
#define SPAD 68
#define SKP 68   // MUST be a multiple of 4: float4 row reads need 16B alignment
#define ATTN_SMEM ((3 * BQ * SPAD + HDv * SKP) * (int)sizeof(float))

__global__ __launch_bounds__(256) void attn_kernel(
    const float* __restrict__ Q, const float* __restrict__ K,
    const float* __restrict__ V, float* __restrict__ O)
{
    extern __shared__ float smf[];
    float* sQ  = smf;                       // [64][SPAD]
    float* sKT = sQ + BQ * SPAD;            // [HD=64][SKP]  (transposed)
    float* sV  = sKT + HDv * SKP;           // [64][SPAD]
    float* sP  = sV + BKV * SPAD;           // [64][SPAD]

    const int tid = threadIdx.x;
    const int bh  = blockIdx.y;
    const int b   = bh / Hv;
    const int h   = bh % Hv;
    const int q0  = blockIdx.x * BQ;

    const int tq = tid >> 4;   // 0..15
    const int tj = tid & 15;   // 0..15

    const float* Qb = Q + ((size_t)b * Tv) * Dv + h * HDv;
    const float* Kb = K + ((size_t)b * Tv) * Dv + h * HDv;
    const float* Vb = V + ((size_t)b * Tv) * Dv + h * HDv;

    #pragma unroll
    for (int i = 0; i < 4; i++) {
        int f  = tid + i * 256;
        int r  = f >> 4;
        int cc = (f & 15) * 4;
        *(float4*)&sQ[r * SPAD + cc] =
            *(const float4*)(Qb + (size_t)(q0 + r) * Dv + cc);
    }

    float m_i[4], l_i[4], acc[4][4];
    #pragma unroll
    for (int qq = 0; qq < 4; qq++) {
        m_i[qq] = -1e30f; l_i[qq] = 0.f;
        #pragma unroll
        for (int dd = 0; dd < 4; dd++) acc[qq][dd] = 0.f;
    }

    for (int kv0 = 0; kv0 < Tv; kv0 += BKV) {
        __syncthreads();
        #pragma unroll
        for (int i = 0; i < 4; i++) {
            int f  = tid + i * 256;
            int r  = f >> 4;
            int cc = (f & 15) * 4;
            float4 tk = *(const float4*)(Kb + (size_t)(kv0 + r) * Dv + cc);
            sKT[(cc + 0) * SKP + r] = tk.x;
            sKT[(cc + 1) * SKP + r] = tk.y;
            sKT[(cc + 2) * SKP + r] = tk.z;
            sKT[(cc + 3) * SKP + r] = tk.w;
            *(float4*)&sV[r * SPAD + cc] =
                *(const float4*)(Vb + (size_t)(kv0 + r) * Dv + cc);
        }
        __syncthreads();

        float s[4][4];
        #pragma unroll
        for (int qq = 0; qq < 4; qq++)
            #pragma unroll
            for (int jj = 0; jj < 4; jj++) s[qq][jj] = 0.f;

        #pragma unroll 4
        for (int d4 = 0; d4 < 16; d4++) {
            float qv[4][4], kt[4][4];
            #pragma unroll
            for (int qq = 0; qq < 4; qq++) {
                float4 t = *(const float4*)&sQ[(4 * tq + qq) * SPAD + 4 * d4];
                qv[qq][0] = t.x; qv[qq][1] = t.y; qv[qq][2] = t.z; qv[qq][3] = t.w;
            }
            #pragma unroll
            for (int dd = 0; dd < 4; dd++) {
                float4 t = *(const float4*)&sKT[(4 * d4 + dd) * SKP + 4 * tj];
                kt[dd][0] = t.x; kt[dd][1] = t.y; kt[dd][2] = t.z; kt[dd][3] = t.w;
            }
            #pragma unroll
            for (int qq = 0; qq < 4; qq++)
                #pragma unroll
                for (int jj = 0; jj < 4; jj++)
                    #pragma unroll
                    for (int dd = 0; dd < 4; dd++)
                        s[qq][jj] += qv[qq][dd] * kt[dd][jj];
        }

        #pragma unroll
        for (int qq = 0; qq < 4; qq++) {
            float mx = -1e30f;
            #pragma unroll
            for (int jj = 0; jj < 4; jj++) {
                s[qq][jj] *= 0.125f;
                mx = fmaxf(mx, s[qq][jj]);
            }
            #pragma unroll
            for (int off = 8; off > 0; off >>= 1)
                mx = fmaxf(mx, __shfl_xor_sync(0xffffffffu, mx, off));

            float mnew  = fmaxf(m_i[qq], mx);
            float alpha = __expf(m_i[qq] - mnew);
            m_i[qq] = mnew;

            float lsum = 0.f;
            #pragma unroll
            for (int jj = 0; jj < 4; jj++) {
                float p = __expf(s[qq][jj] - mnew);
                s[qq][jj] = p;
                lsum += p;
            }
            l_i[qq] = l_i[qq] * alpha + lsum;
            #pragma unroll
            for (int dd = 0; dd < 4; dd++) acc[qq][dd] *= alpha;
        }

        #pragma unroll
        for (int qq = 0; qq < 4; qq++) {
            float4 t;
            t.x = s[qq][0]; t.y = s[qq][1]; t.z = s[qq][2]; t.w = s[qq][3];
            *(float4*)&sP[(4 * tq + qq) * SPAD + 4 * tj] = t;
        }
        __syncthreads();

        #pragma unroll 4
        for (int j4 = 0; j4 < 16; j4++) {
            float p[4][4], vv[4][4];
            #pragma unroll
            for (int qq = 0; qq < 4; qq++) {
                float4 t = *(const float4*)&sP[(4 * tq + qq) * SPAD + 4 * j4];
                p[qq][0] = t.x; p[qq][1] = t.y; p[qq][2] = t.z; p[qq][3] = t.w;
            }
            #pragma unroll
            for (int jj = 0; jj < 4; jj++) {
                float4 t = *(const float4*)&sV[(4 * j4 + jj) * SPAD + 4 * tj];
                vv[jj][0] = t.x; vv[jj][1] = t.y; vv[jj][2] = t.z; vv[jj][3] = t.w;
            }
            #pragma unroll
            for (int qq = 0; qq < 4; qq++)
                #pragma unroll
                for (int dd = 0; dd < 4; dd++)
                    #pragma unroll
                    for (int jj = 0; jj < 4; jj++)
                        acc[qq][dd] += p[qq][jj] * vv[jj][dd];
        }
    }

    float* Ob = O + ((size_t)b * Tv) * Dv + h * HDv;
    #pragma unroll
    for (int qq = 0; qq < 4; qq++) {
        float l = l_i[qq];
        #pragma unroll
        for (int off = 8; off > 0; off >>= 1)
            l += __shfl_xor_sync(0xffffffffu, l, off);
        float inv = 1.0f / l;
        float4 o;
        o.x = acc[qq][0] * inv; o.y = acc[qq][1] * inv;
        o.z = acc[qq][2] * inv; o.w = acc[qq][3] * inv;
        *(float4*)(Ob + (size_t)(q0 + 4 * tq + qq) * Dv + 4 * tj) = o;
    }
}

// ================= launch =================
extern "C" void kernel_launch(void* const* d_in, const int* in_sizes, int n_in,
                              void* d_out, int out_size)
{
    const float* x  = (const float*)d_in[0];
    const float* Wq = (const float*)d_in[1];
    const float* bq = (const float*)d_in[2];
    const float* Wk = (const float*)d_in[3];
    const float* bk = (const float*)d_in[4];
    const float* Wv = (const float*)d_in[5];
    const float* bv = (const float*)d_in[6];
    const float* Wo = (const float*)d_in[7];
    const float* bo = (const float*)d_in[8];
    float* out = (float*)d_out;

    float *q, *k, *v, *o;
    cudaGetSymbolAddress((void**)&q, g_q);
    cudaGetSymbolAddress((void**)&k, g_k);
    cudaGetSymbolAddress((void**)&v, g_v);
    cudaGetSymbolAddress((void**)&o, g_o);

    cudaFuncSetAttribute(gemm_mma,
                         cudaFuncAttributeMaxDynamicSharedMemorySize, GSMEM);
    cudaFuncSetAttribute(attn_kernel,
                         cudaFuncAttributeMaxDynamicSharedMemorySize, ATTN_SMEM);

    dim3 ggrid(Dv / 128, MTOK / 128);   // (8, 64)
    gemm_mma<<<ggrid, 256, GSMEM>>>(x, Wq, bq, q);
    gemm_mma<<<ggrid, 256, GSMEM>>>(x, Wk, bk, k);
    gemm_mma<<<ggrid, 256, GSMEM>>>(x, Wv, bv, v);

    dim3 agrid(Tv / BQ, Bv * Hv);       // (32, 64)
    attn_kernel<<<agrid, 256, ATTN_SMEM>>>(q, k, v, o);

    gemm_mma<<<ggrid, 256, GSMEM>>>(o, Wo, bo, out);
}

// round 7
// speedup vs baseline: 3.3686x; 1.7738x over previous
#include <cuda_runtime.h>
#include <cuda_bf16.h>
#include <stdint.h>

// Problem constants
#define Bv 4
#define Tv 2048
#define Dv 1024
#define Hv 16
#define HDv 64
#define MTOK (Bv*Tv)          // 8192 rows

// ---------------- scratch (no allocation allowed) ----------------
__device__ float g_q[(size_t)MTOK * Dv];
__device__ float g_k[(size_t)MTOK * Dv];
__device__ float g_v[(size_t)MTOK * Dv];
__device__ float g_o[(size_t)MTOK * Dv];

// ================= helpers =================
__device__ __forceinline__ uint32_t smem_u32(const void* p) {
    uint32_t a;
    asm("{ .reg .u64 t; cvta.to.shared.u64 t, %1; cvt.u32.u64 %0, t; }"
        : "=r"(a) : "l"(p));
    return a;
}

#define SW128(o) ((o) ^ (((o) >> 3) & 0x70))

#define LDSM4(r, addr) \
    asm volatile("ldmatrix.sync.aligned.m8n8.x4.shared.b16 {%0,%1,%2,%3}, [%4];" \
        : "=r"((r)[0]), "=r"((r)[1]), "=r"((r)[2]), "=r"((r)[3]) : "r"(addr))

#define LDSM2(r, addr) \
    asm volatile("ldmatrix.sync.aligned.m8n8.x2.shared.b16 {%0,%1}, [%2];" \
        : "=r"((r)[0]), "=r"((r)[1]) : "r"(addr))

#define LDSM2T(r, addr) \
    asm volatile("ldmatrix.sync.aligned.m8n8.x2.trans.shared.b16 {%0,%1}, [%2];" \
        : "=r"((r)[0]), "=r"((r)[1]) : "r"(addr))

#define MMA_BF16(d, a, b) \
    asm volatile("mma.sync.aligned.m16n8k16.row.col.f32.bf16.bf16.f32 " \
        "{%0,%1,%2,%3}, {%4,%5,%6,%7}, {%8,%9}, {%0,%1,%2,%3};" \
        : "+f"((d)[0]), "+f"((d)[1]), "+f"((d)[2]), "+f"((d)[3]) \
        : "r"((a)[0]), "r"((a)[1]), "r"((a)[2]), "r"((a)[3]), \
          "r"((b)[0]), "r"((b)[1]))

// split fp32 -> (hi, lo) bf16 pairs, packed for 8B smem stores
__device__ __forceinline__ void split4(float4 v, uint2& h, uint2& l) {
    __nv_bfloat16 hx = __float2bfloat16_rn(v.x);
    __nv_bfloat16 hy = __float2bfloat16_rn(v.y);
    __nv_bfloat16 hz = __float2bfloat16_rn(v.z);
    __nv_bfloat16 hw = __float2bfloat16_rn(v.w);
    __nv_bfloat162 h0; h0.x = hx; h0.y = hy;
    __nv_bfloat162 h1; h1.x = hz; h1.y = hw;
    __nv_bfloat162 l0;
    l0.x = __float2bfloat16_rn(v.x - __bfloat162float(hx));
    l0.y = __float2bfloat16_rn(v.y - __bfloat162float(hy));
    __nv_bfloat162 l1;
    l1.x = __float2bfloat16_rn(v.z - __bfloat162float(hz));
    l1.y = __float2bfloat16_rn(v.w - __bfloat162float(hw));
    h.x = *reinterpret_cast<uint32_t*>(&h0);
    h.y = *reinterpret_cast<uint32_t*>(&h1);
    l.x = *reinterpret_cast<uint32_t*>(&l0);
    l.y = *reinterpret_cast<uint32_t*>(&l1);
}

// pack two floats -> bf16x2 hi + bf16x2 residual
__device__ __forceinline__ void packsplit2(float p0, float p1,
                                           uint32_t& h, uint32_t& l) {
    __nv_bfloat162 hh;
    hh.x = __float2bfloat16_rn(p0);
    hh.y = __float2bfloat16_rn(p1);
    __nv_bfloat162 ll;
    ll.x = __float2bfloat16_rn(p0 - __bfloat162float(hh.x));
    ll.y = __float2bfloat16_rn(p1 - __bfloat162float(hh.y));
    h = *reinterpret_cast<uint32_t*>(&hh);
    l = *reinterpret_cast<uint32_t*>(&ll);
}

// ================= HMMA GEMM: C[M,1024] = A[M,1024] @ W[1024,1024]^T + bias =================
#define GT 16384
#define GSMEM (4 * GT + 1024)

__global__ __launch_bounds__(256) void gemm_mma(
    const float* __restrict__ A, const float* __restrict__ W,
    const float* __restrict__ bias, float* __restrict__ C)
{
    extern __shared__ char dsm[];
    uint32_t dynb = smem_u32(dsm);
    uint32_t base = (dynb + 1023) & ~1023u;
    char* st = dsm + (base - dynb);
    const uint32_t sb = base;

    const int tid  = threadIdx.x;
    const int wid  = tid >> 5;
    const int lane = tid & 31;
    const int wm   = wid >> 2;
    const int wn   = wid & 3;

    const int rowBase = blockIdx.y * 128;
    const int colBase = blockIdx.x * 128;
    const float* Ab = A + (size_t)rowBase * Dv;
    const float* Wb = W + (size_t)colBase * Dv;

    const int r0 = tid >> 4;
    const int c4 = (tid & 15) * 4;

    float acc[4][4][4];
    #pragma unroll
    for (int mt = 0; mt < 4; mt++)
        #pragma unroll
        for (int nt = 0; nt < 4; nt++)
            #pragma unroll
            for (int j = 0; j < 4; j++) acc[mt][nt][j] = 0.f;

    float4 av[8], wv[8];
    #pragma unroll
    for (int i = 0; i < 8; i++) {
        av[i] = *(const float4*)(Ab + (size_t)(r0 + 16 * i) * Dv + c4);
        wv[i] = *(const float4*)(Wb + (size_t)(r0 + 16 * i) * Dv + c4);
    }

    for (int c = 0; c < 16; c++) {
        __syncthreads();

        #pragma unroll
        for (int i = 0; i < 8; i++) {
            int row = r0 + 16 * i;
            uint32_t off = SW128((uint32_t)(row * 128 + (tid & 15) * 8));
            uint2 h, l;
            split4(av[i], h, l);
            *(uint2*)(st + off)          = h;
            *(uint2*)(st + GT + off)     = l;
            split4(wv[i], h, l);
            *(uint2*)(st + 2 * GT + off) = h;
            *(uint2*)(st + 3 * GT + off) = l;
        }
        __syncthreads();

        if (c < 15) {
            const float* Ap = Ab + (c + 1) * 64 + c4;
            const float* Wp = Wb + (c + 1) * 64 + c4;
            #pragma unroll
            for (int i = 0; i < 8; i++) {
                av[i] = *(const float4*)(Ap + (size_t)(r0 + 16 * i) * Dv);
                wv[i] = *(const float4*)(Wp + (size_t)(r0 + 16 * i) * Dv);
            }
        }

        #pragma unroll
        for (int ks = 0; ks < 4; ks++) {
            uint32_t aH[4][4], aL[4][4], bH[4][2], bL[4][2];

            const int arow = wm * 64 + (lane & 15);
            const uint32_t akb = ks * 32 + ((lane >> 4) << 4);
            #pragma unroll
            for (int mt = 0; mt < 4; mt++) {
                uint32_t o = SW128((uint32_t)((arow + mt * 16) * 128) + akb);
                LDSM4(aH[mt], sb + o);
                LDSM4(aL[mt], sb + GT + o);
            }

            const int brow = wn * 32 + (lane & 7);
            const uint32_t bkb = ks * 32 + ((lane >> 3) & 1) * 16;
            #pragma unroll
            for (int nt = 0; nt < 4; nt++) {
                uint32_t o = SW128((uint32_t)((brow + nt * 8) * 128) + bkb);
                LDSM2(bH[nt], sb + 2 * GT + o);
                LDSM2(bL[nt], sb + 3 * GT + o);
            }

            #pragma unroll
            for (int mt = 0; mt < 4; mt++)
                #pragma unroll
                for (int nt = 0; nt < 4; nt++) {
                    MMA_BF16(acc[mt][nt], aH[mt], bH[nt]);
                    MMA_BF16(acc[mt][nt], aH[mt], bL[nt]);
                    MMA_BF16(acc[mt][nt], aL[mt], bH[nt]);
                }
        }
    }

    #pragma unroll
    for (int mt = 0; mt < 4; mt++) {
        #pragma unroll
        for (int nt = 0; nt < 4; nt++) {
            int row = rowBase + wm * 64 + mt * 16 + (lane >> 2);
            int col = colBase + wn * 32 + nt * 8 + (lane & 3) * 2;
            float2 b2 = *(const float2*)(bias + col);
            float2 o0, o1;
            o0.x = acc[mt][nt][0] + b2.x; o0.y = acc[mt][nt][1] + b2.y;
            o1.x = acc[mt][nt][2] + b2.x; o1.y = acc[mt][nt][3] + b2.y;
            *(float2*)(C + (size_t)row * Dv + col)       = o0;
            *(float2*)(C + (size_t)(row + 8) * Dv + col) = o1;
        }
    }
}

// ================= HMMA flash attention =================
// BQ=128 queries/CTA, BKV=64 keys/tile, 8 warps (16 query rows each).
// smem (bf16, SW128, 128B rows of 64 elems):
//   QH 16K | QL 16K | KH 8K | KL 8K | VH 8K | VL 8K  = 64K
#define AQH 0
#define AQL 16384
#define AKH 32768
#define AKL 40960
#define AVH 49152
#define AVL 57344
#define ASMEM (65536 + 1024)

__global__ __launch_bounds__(256) void attn_mma(
    const float* __restrict__ Q, const float* __restrict__ K,
    const float* __restrict__ V, float* __restrict__ O)
{
    extern __shared__ char dsm[];
    uint32_t dynb = smem_u32(dsm);
    uint32_t base = (dynb + 1023) & ~1023u;
    char* st = dsm + (base - dynb);
    const uint32_t sb = base;

    const int tid  = threadIdx.x;
    const int wid  = tid >> 5;
    const int lane = tid & 31;

    const int bh = blockIdx.y;
    const int b  = bh / Hv;
    const int h  = bh % Hv;
    const int q0 = blockIdx.x * 128;

    const float* Qb = Q + ((size_t)b * Tv) * Dv + h * HDv;
    const float* Kb = K + ((size_t)b * Tv) * Dv + h * HDv;
    const float* Vb = V + ((size_t)b * Tv) * Dv + h * HDv;

    // ---- load Q tile [128 x 64], scale by 1/8, split hi/lo ----
    #pragma unroll
    for (int i = 0; i < 8; i++) {
        int f   = tid + i * 256;
        int row = f >> 4;
        int c4  = (f & 15) * 4;
        float4 v = *(const float4*)(Qb + (size_t)(q0 + row) * Dv + c4);
        v.x *= 0.125f; v.y *= 0.125f; v.z *= 0.125f; v.w *= 0.125f;
        uint2 hh, ll;
        split4(v, hh, ll);
        uint32_t off = SW128((uint32_t)(row * 128 + c4 * 2));
        *(uint2*)(st + AQH + off) = hh;
        *(uint2*)(st + AQL + off) = ll;
    }

    float oc[8][4];
    #pragma unroll
    for (int j = 0; j < 8; j++)
        #pragma unroll
        for (int t = 0; t < 4; t++) oc[j][t] = 0.f;
    float m0 = -1e30f, m1 = -1e30f, l0 = 0.f, l1 = 0.f;

    const int mrow = wid * 16 + (lane & 15);              // A-frag row addr
    const uint32_t akhi = (uint32_t)((lane >> 4) << 4);   // lanes16-31: +16B (k+8)

    for (int kv0 = 0; kv0 < Tv; kv0 += 64) {
        __syncthreads();   // prev iter done reading K/V (also covers Q, iter 0)

        // ---- load K,V tiles [64 x 64], split hi/lo ----
        #pragma unroll
        for (int i = 0; i < 4; i++) {
            int f   = tid + i * 256;
            int row = f >> 4;
            int c4  = (f & 15) * 4;
            uint32_t off = SW128((uint32_t)(row * 128 + c4 * 2));
            uint2 hh, ll;
            float4 kv4 = *(const float4*)(Kb + (size_t)(kv0 + row) * Dv + c4);
            split4(kv4, hh, ll);
            *(uint2*)(st + AKH + off) = hh;
            *(uint2*)(st + AKL + off) = ll;
            float4 vv4 = *(const float4*)(Vb + (size_t)(kv0 + row) * Dv + c4);
            split4(vv4, hh, ll);
            *(uint2*)(st + AVH + off) = hh;
            *(uint2*)(st + AVL + off) = ll;
        }
        __syncthreads();

        // ---- S = Q K^T (pre-scaled), fp32 accum, split-bf16 ----
        float sc[8][4];
        #pragma unroll
        for (int j = 0; j < 8; j++)
            #pragma unroll
            for (int t = 0; t < 4; t++) sc[j][t] = 0.f;

        #pragma unroll
        for (int ks = 0; ks < 4; ks++) {
            uint32_t qh[4], ql[4];
            uint32_t ao = SW128((uint32_t)(mrow * 128) + ks * 32 + akhi);
            LDSM4(qh, sb + AQH + ao);
            LDSM4(ql, sb + AQL + ao);

            #pragma unroll
            for (int j = 0; j < 8; j++) {
                uint32_t kh[2], kl[2];
                int krow = j * 8 + (lane & 7);
                uint32_t bo = SW128((uint32_t)(krow * 128) + ks * 32 +
                                    ((lane >> 3) & 1) * 16);
                LDSM2(kh, sb + AKH + bo);
                LDSM2(kl, sb + AKL + bo);
                MMA_BF16(sc[j], qh, kh);
                MMA_BF16(sc[j], qh, kl);
                MMA_BF16(sc[j], ql, kh);
            }
        }

        // ---- online softmax on fragments (rows: lane>>2 and +8) ----
        float mx0 = -1e30f, mx1 = -1e30f;
        #pragma unroll
        for (int j = 0; j < 8; j++) {
            mx0 = fmaxf(mx0, fmaxf(sc[j][0], sc[j][1]));
            mx1 = fmaxf(mx1, fmaxf(sc[j][2], sc[j][3]));
        }
        mx0 = fmaxf(mx0, __shfl_xor_sync(0xffffffffu, mx0, 1));
        mx0 = fmaxf(mx0, __shfl_xor_sync(0xffffffffu, mx0, 2));
        mx1 = fmaxf(mx1, __shfl_xor_sync(0xffffffffu, mx1, 1));
        mx1 = fmaxf(mx1, __shfl_xor_sync(0xffffffffu, mx1, 2));

        float mn0 = fmaxf(m0, mx0);
        float mn1 = fmaxf(m1, mx1);
        float a0f = __expf(m0 - mn0);
        float a1f = __expf(m1 - mn1);
        m0 = mn0; m1 = mn1;

        float ls0 = 0.f, ls1 = 0.f;
        #pragma unroll
        for (int j = 0; j < 8; j++) {
            sc[j][0] = __expf(sc[j][0] - m0);
            sc[j][1] = __expf(sc[j][1] - m0);
            sc[j][2] = __expf(sc[j][2] - m1);
            sc[j][3] = __expf(sc[j][3] - m1);
            ls0 += sc[j][0] + sc[j][1];
            ls1 += sc[j][2] + sc[j][3];
        }
        l0 = l0 * a0f + ls0;
        l1 = l1 * a1f + ls1;

        #pragma unroll
        for (int j = 0; j < 8; j++) {
            oc[j][0] *= a0f; oc[j][1] *= a0f;
            oc[j][2] *= a1f; oc[j][3] *= a1f;
        }

        // ---- O += P V : P from C-frags (split hi/lo), V via trans ldmatrix ----
        #pragma unroll
        for (int ks = 0; ks < 4; ks++) {
            uint32_t ah[4], al[4];
            packsplit2(sc[2*ks  ][0], sc[2*ks  ][1], ah[0], al[0]);
            packsplit2(sc[2*ks  ][2], sc[2*ks  ][3], ah[1], al[1]);
            packsplit2(sc[2*ks+1][0], sc[2*ks+1][1], ah[2], al[2]);
            packsplit2(sc[2*ks+1][2], sc[2*ks+1][3], ah[3], al[3]);

            int vrow = ks * 16 + (lane & 15);
            #pragma unroll
            for (int j = 0; j < 8; j++) {
                uint32_t vh[2], vl[2];
                uint32_t vo = SW128((uint32_t)(vrow * 128) + j * 16);
                LDSM2T(vh, sb + AVH + vo);
                LDSM2T(vl, sb + AVL + vo);
                MMA_BF16(oc[j], ah, vh);
                MMA_BF16(oc[j], ah, vl);
                MMA_BF16(oc[j], al, vh);
            }
        }
    }

    // ---- finalize: divide by row sums, write O ----
    l0 += __shfl_xor_sync(0xffffffffu, l0, 1);
    l0 += __shfl_xor_sync(0xffffffffu, l0, 2);
    l1 += __shfl_xor_sync(0xffffffffu, l1, 1);
    l1 += __shfl_xor_sync(0xffffffffu, l1, 2);
    float inv0 = 1.0f / l0;
    float inv1 = 1.0f / l1;

    const int r0g = q0 + wid * 16 + (lane >> 2);
    float* Ob = O + ((size_t)b * Tv) * Dv + h * HDv;
    #pragma unroll
    for (int j = 0; j < 8; j++) {
        int col = j * 8 + (lane & 3) * 2;
        float2 w0, w1;
        w0.x = oc[j][0] * inv0; w0.y = oc[j][1] * inv0;
        w1.x = oc[j][2] * inv1; w1.y = oc[j][3] * inv1;
        *(float2*)(Ob + (size_t)r0g * Dv + col)       = w0;
        *(float2*)(Ob + (size_t)(r0g + 8) * Dv + col) = w1;
    }
}

// ================= launch =================
extern "C" void kernel_launch(void* const* d_in, const int* in_sizes, int n_in,
                              void* d_out, int out_size)
{
    const float* x  = (const float*)d_in[0];
    const float* Wq = (const float*)d_in[1];
    const float* bq = (const float*)d_in[2];
    const float* Wk = (const float*)d_in[3];
    const float* bk = (const float*)d_in[4];
    const float* Wv = (const float*)d_in[5];
    const float* bv = (const float*)d_in[6];
    const float* Wo = (const float*)d_in[7];
    const float* bo = (const float*)d_in[8];
    float* out = (float*)d_out;

    float *q, *k, *v, *o;
    cudaGetSymbolAddress((void**)&q, g_q);
    cudaGetSymbolAddress((void**)&k, g_k);
    cudaGetSymbolAddress((void**)&v, g_v);
    cudaGetSymbolAddress((void**)&o, g_o);

    cudaFuncSetAttribute(gemm_mma,
                         cudaFuncAttributeMaxDynamicSharedMemorySize, GSMEM);
    cudaFuncSetAttribute(attn_mma,
                         cudaFuncAttributeMaxDynamicSharedMemorySize, ASMEM);

    dim3 ggrid(Dv / 128, MTOK / 128);   // (8, 64)
    gemm_mma<<<ggrid, 256, GSMEM>>>(x, Wq, bq, q);
    gemm_mma<<<ggrid, 256, GSMEM>>>(x, Wk, bk, k);
    gemm_mma<<<ggrid, 256, GSMEM>>>(x, Wv, bv, v);

    dim3 agrid(Tv / 128, Bv * Hv);      // (16, 64)
    attn_mma<<<agrid, 256, ASMEM>>>(q, k, v, o);

    gemm_mma<<<ggrid, 256, GSMEM>>>(o, Wo, bo, out);
}